// round 13
// baseline (speedup 1.0000x reference)
#include <cuda_runtime.h>
#include <math.h>

#define BB 128
#define SS 512
#define DD 768
#define PP 60
#define LL 5
#define KK 5
#define D4 (DD/4)            // 192
#define SEQ_OUT (KK*LL + SS) // 537
#define NCHUNK 16
#define CHUNK_S (SS/NCHUNK)  // 32

#define MAP_SCALE 0.1f
#define MAX_NORM (1.0f - 4e-3f)

// Output layout (float32, concatenated in reference return order)
#define N_PE    ((long long)BB*SEQ_OUT*DD)           // 52,801,536
#define OFF_RS  (N_PE)
#define OFF_IDX (OFF_RS + 1)
#define OFF_SIM (OFF_IDX + (long long)BB*KK)
#define OFF_SK  (OFF_SIM + (long long)BB*PP)

// Scratch (device globals -> no allocation)
__device__ float g_xpart[BB*NCHUNK*DD];
__device__ float g_kcoef[PP];
__device__ float g_persum[BB];
__device__ int   g_idx[BB*KK];

// ---------------------------------------------------------------------------
// Kernel 1: copy x_embed into prompted_embedding slot + per-chunk partial sums
// grid (NCHUNK, BB), 192 threads. UNTOUCHED (32 regs, 75.9% DRAM, 6.0 TB/s).
// ---------------------------------------------------------------------------
__global__ void k1_copy_partial(const float4* __restrict__ xe, float4* __restrict__ out) {
    int chunk = blockIdx.x, b = blockIdx.y, t = threadIdx.x;
    const float4* src = xe + ((size_t)b * SS + (size_t)chunk * CHUNK_S) * D4 + t;
    float4* dst = out + ((size_t)b * SEQ_OUT + KK*LL + (size_t)chunk * CHUNK_S) * D4 + t;
    float4 acc = make_float4(0.f, 0.f, 0.f, 0.f);
#pragma unroll 8
    for (int s = 0; s < CHUNK_S; s++) {
        float4 v = src[(size_t)s * D4];
        acc.x += v.x; acc.y += v.y; acc.z += v.z; acc.w += v.w;
        dst[(size_t)s * D4] = v;
    }
    ((float4*)g_xpart)[(b * NCHUNK + chunk) * D4 + t] = acc;
}

// ---------------------------------------------------------------------------
// Kernel 2: per-batch mean -> map_to_ball -> per-key (ssq+dot in one pass) ->
// distances -> similarity -> top-K -> idx. 128 blocks x 512 threads (16 warps).
// ---------------------------------------------------------------------------
__global__ void k2_dist_topk(const float4* __restrict__ pkey, float* __restrict__ out) {
    int b = blockIdx.x;
    int tid = threadIdx.x, lane = tid & 31, warp = tid >> 5;
    __shared__ float4 qsh4[D4];
    __shared__ float dsh[PP];
    __shared__ float redsh[16];
    __shared__ float x2sh;

    // ---- mean from partials (threads 0..383 handle 2 dims each as float2) ----
    float local = 0.f;
    if (tid < 384) {
        float sx = 0.f, sy = 0.f;
        const float2* pp = (const float2*)g_xpart;
#pragma unroll
        for (int c = 0; c < NCHUNK; c++) {
            float2 a = pp[(size_t)(b * NCHUNK + c) * (DD/2) + tid];
            sx += a.x; sy += a.y;
        }
        sx *= (1.0f / (float)SS);
        sy *= (1.0f / (float)SS);
        ((float2*)qsh4)[tid] = make_float2(sx, sy);
        local = sx*sx + sy*sy;
    }
#pragma unroll
    for (int o = 16; o > 0; o >>= 1) local += __shfl_xor_sync(0xffffffffu, local, o);
    if (lane == 0) redsh[warp] = local;
    __syncthreads();
    if (tid == 0) {
        float ssq = 0.f;
#pragma unroll
        for (int i = 0; i < 16; i++) ssq += redsh[i];
        float inv = rsqrtf(fmaxf(ssq, 1e-12f));
        float n = sqrtf(fmaxf(ssq * inv * inv * (MAP_SCALE*MAP_SCALE), 1e-15f));
        float th = tanhf(n);
        float factor = (th > MAX_NORM) ? (MAX_NORM / th) : 1.0f;
        float nf = th * factor;
        x2sh = nf * nf;
        redsh[0] = inv * MAP_SCALE * (th / n) * factor;
    }
    __syncthreads();
    float coeffq = redsh[0];
    if (tid < 384) {
        float2 q = ((float2*)qsh4)[tid];
        ((float2*)qsh4)[tid] = make_float2(q.x * coeffq, q.y * coeffq);
    }
    __syncthreads();
    float x2 = x2sh;

    // ---- warp-per-key: ssq + dot in one pass (4 rounds of 16 warps) ----
    for (int p = warp; p < PP; p += 16) {
        const float4* kr = pkey + (size_t)p * D4;
        float dot = 0.f, ssq = 0.f;
#pragma unroll
        for (int i = 0; i < 6; i++) {
            int j = lane + 32 * i;
            float4 kv = kr[j];
            float4 qv = qsh4[j];
            dot += kv.x*qv.x + kv.y*qv.y + kv.z*qv.z + kv.w*qv.w;
            ssq += kv.x*kv.x + kv.y*kv.y + kv.z*kv.z + kv.w*kv.w;
        }
#pragma unroll
        for (int o = 16; o > 0; o >>= 1) {
            dot += __shfl_xor_sync(0xffffffffu, dot, o);
            ssq += __shfl_xor_sync(0xffffffffu, ssq, o);
        }
        if (lane == 0) {
            float inv = rsqrtf(fmaxf(ssq, 1e-12f));
            float n = sqrtf(fmaxf(ssq * inv * inv * (MAP_SCALE*MAP_SCALE), 1e-15f));
            float th = tanhf(n);
            float factor = (th > MAX_NORM) ? (MAX_NORM / th) : 1.0f;
            float coeffk = inv * MAP_SCALE * (th / n) * factor;
            float nf = th * factor;
            float y2 = nf * nf;
            if (b == 0) g_kcoef[p] = coeffk;   // publish once for k3
            float xy = dot * coeffk;           // dot(q_ball, key_ball)
            float A   = 1.f - 2.f*xy + y2;
            float Bc  = 1.f - x2;
            float den = fmaxf(1.f - 2.f*xy + x2*y2, 1e-15f);
            float n2  = (A*A*x2 - 2.f*A*Bc*xy + Bc*Bc*y2) / (den*den);
            float nn  = sqrtf(fmaxf(n2, 1e-15f));
            nn = fminf(nn, 1.f - 1e-7f);
            float dist = 2.f * atanhf(nn);
            dsh[p] = dist;
            out[OFF_SIM + (long long)b * PP + p] = -dist;
        }
    }
    __syncthreads();

    // ---- top-K (smallest dist), sorted idx, per-batch selected sum ----
    if (tid == 0) {
        int sel[KK];
        bool used[PP];
        for (int p = 0; p < PP; p++) used[p] = false;
        float sum = 0.f;
        for (int k = 0; k < KK; k++) {
            float best = 1e30f; int bi = 0;
            for (int p = 0; p < PP; p++)
                if (!used[p] && dsh[p] < best) { best = dsh[p]; bi = p; }
            used[bi] = true; sel[k] = bi; sum += best;
        }
        for (int i = 0; i < KK; i++)
            for (int j = i + 1; j < KK; j++)
                if (sel[j] < sel[i]) { int t2 = sel[i]; sel[i] = sel[j]; sel[j] = t2; }
        for (int k = 0; k < KK; k++) {
            g_idx[b * KK + k] = sel[k];
            out[OFF_IDX + (long long)b * KK + k] = (float)sel[k];
        }
        g_persum[b] = sum;
    }
}

// ---------------------------------------------------------------------------
// Kernel 3: gather, one block per batch (128 blocks x 512 threads).
// Fewer/fatter blocks: R2 measured 640 blocks faster than R9's 3840 for the
// same 12 MB (launch/ramp dominates this latency-bound kernel).
// ---------------------------------------------------------------------------
__global__ void k3_gather(const float4* __restrict__ prompt,
                          const float* __restrict__ pkey,
                          float* __restrict__ out) {
    int b = blockIdx.x, tid = threadIdx.x;
    __shared__ int   ish[KK];
    __shared__ float csh[KK];
    if (tid < KK) {
        int j = g_idx[b * KK + tid];
        ish[tid] = j;
        csh[tid] = g_kcoef[j];
    }
    __syncthreads();

    // prompt rows: 25 rows x 192 float4 = 4800 float4
#pragma unroll
    for (int i = tid; i < KK*LL*D4; i += 512) {
        int r = i / D4, c = i % D4;
        int j = ish[r / LL];
        float4 v = prompt[((size_t)j * LL + (r % LL)) * D4 + c];
        ((float4*)out)[((size_t)b * SEQ_OUT + r) * D4 + c] = v;
    }
    // selected_key: 5 x 768 scalars (odd base offset)
#pragma unroll
    for (int i = tid; i < KK*DD; i += 512) {
        int k = i / DD, c = i % DD;
        out[OFF_SK + (size_t)b * KK * DD + i] =
            pkey[(size_t)ish[k] * DD + c] * csh[k];
    }
    if (b == 0 && tid == 0) {
        float s = 0.f;
#pragma unroll 8
        for (int i = 0; i < BB; i++) s += g_persum[i];
        out[OFF_RS] = s * (1.0f / (float)BB);
    }
}

extern "C" void kernel_launch(void* const* d_in, const int* in_sizes, int n_in,
                              void* d_out, int out_size) {
    const float* x_embed = nullptr;    // 128*512*768
    const float* prompt = nullptr;     // 60*5*768
    const float* prompt_key = nullptr; // 60*768
    for (int i = 0; i < n_in; i++) {
        if (in_sizes[i] == BB*SS*DD)        x_embed    = (const float*)d_in[i];
        else if (in_sizes[i] == PP*LL*DD)   prompt     = (const float*)d_in[i];
        else if (in_sizes[i] == PP*DD)      prompt_key = (const float*)d_in[i];
    }
    float* out = (float*)d_out;

    dim3 g1(NCHUNK, BB);
    k1_copy_partial<<<g1, D4>>>((const float4*)x_embed, (float4*)out);
    k2_dist_topk<<<BB, 512>>>((const float4*)prompt_key, out);
    k3_gather<<<BB, 512>>>((const float4*)prompt, prompt_key, out);
}

// round 15
// speedup vs baseline: 1.0166x; 1.0166x over previous
#include <cuda_runtime.h>
#include <math.h>

#define BB 128
#define SS 512
#define DD 768
#define PP 60
#define LL 5
#define KK 5
#define D4 (DD/4)            // 192
#define SEQ_OUT (KK*LL + SS) // 537
#define NCHUNK 16
#define CHUNK_S (SS/NCHUNK)  // 32

#define MAP_SCALE 0.1f
#define MAX_NORM (1.0f - 4e-3f)

// Output layout (float32, concatenated in reference return order)
#define N_PE    ((long long)BB*SEQ_OUT*DD)           // 52,801,536
#define OFF_RS  (N_PE)
#define OFF_IDX (OFF_RS + 1)
#define OFF_SIM (OFF_IDX + (long long)BB*KK)
#define OFF_SK  (OFF_SIM + (long long)BB*PP)

// Scratch (device globals -> no allocation)
__device__ float g_xpart[BB*NCHUNK*DD];
__device__ float g_kcoef[PP];
__device__ float g_persum[BB];
__device__ int   g_idx[BB*KK];

// ---------------------------------------------------------------------------
// Kernel 1: copy x_embed into prompted_embedding slot + per-chunk partial sums
// grid (NCHUNK, BB), 192 threads. UNTOUCHED hot loop (32 regs, 76% DRAM).
// Ends with a PDL trigger so k2 can launch while k1 drains.
// ---------------------------------------------------------------------------
__global__ void k1_copy_partial(const float4* __restrict__ xe, float4* __restrict__ out) {
    int chunk = blockIdx.x, b = blockIdx.y, t = threadIdx.x;
    const float4* src = xe + ((size_t)b * SS + (size_t)chunk * CHUNK_S) * D4 + t;
    float4* dst = out + ((size_t)b * SEQ_OUT + KK*LL + (size_t)chunk * CHUNK_S) * D4 + t;
    float4 acc = make_float4(0.f, 0.f, 0.f, 0.f);
#pragma unroll 8
    for (int s = 0; s < CHUNK_S; s++) {
        float4 v = src[(size_t)s * D4];
        acc.x += v.x; acc.y += v.y; acc.z += v.z; acc.w += v.w;
        dst[(size_t)s * D4] = v;
    }
    ((float4*)g_xpart)[(b * NCHUNK + chunk) * D4 + t] = acc;
#if __CUDA_ARCH__ >= 900
    cudaTriggerProgrammaticLaunchCompletion();
#endif
}

// ---------------------------------------------------------------------------
// Kernel 2: PDL secondary. Pre-sync prologue computes per-key ssq (independent
// of k1, warms L2 with pkey). Post-sync: mean -> map_to_ball -> dots ->
// distances -> similarity -> top-K -> idx. 128 blocks x 512 threads.
// Ends with a PDL trigger for k3.
// ---------------------------------------------------------------------------
__global__ void k2_dist_topk(const float4* __restrict__ pkey, float* __restrict__ out) {
    int b = blockIdx.x;
    int tid = threadIdx.x, lane = tid & 31, warp = tid >> 5;
    __shared__ float4 qsh4[D4];
    __shared__ float dsh[PP];
    __shared__ float kssq[PP];
    __shared__ float redsh[16];
    __shared__ float x2sh;

    // ---- PRE-SYNC prologue: per-key ssq (no k1 dependency) ----
    for (int p = warp; p < PP; p += 16) {
        const float4* kr = pkey + (size_t)p * D4;
        float ssq = 0.f;
#pragma unroll
        for (int i = 0; i < 6; i++) {
            float4 kv = kr[lane + 32 * i];
            ssq += kv.x*kv.x + kv.y*kv.y + kv.z*kv.z + kv.w*kv.w;
        }
#pragma unroll
        for (int o = 16; o > 0; o >>= 1) ssq += __shfl_xor_sync(0xffffffffu, ssq, o);
        if (lane == 0) kssq[p] = ssq;
    }

#if __CUDA_ARCH__ >= 900
    cudaGridDependencySynchronize();   // k1's g_xpart now visible
#endif
    __syncthreads();

    // ---- mean from partials (threads 0..383 handle 2 dims each as float2) ----
    float local = 0.f;
    if (tid < 384) {
        float sx = 0.f, sy = 0.f;
        const float2* pp = (const float2*)g_xpart;
#pragma unroll
        for (int c = 0; c < NCHUNK; c++) {
            float2 a = pp[(size_t)(b * NCHUNK + c) * (DD/2) + tid];
            sx += a.x; sy += a.y;
        }
        sx *= (1.0f / (float)SS);
        sy *= (1.0f / (float)SS);
        ((float2*)qsh4)[tid] = make_float2(sx, sy);
        local = sx*sx + sy*sy;
    }
#pragma unroll
    for (int o = 16; o > 0; o >>= 1) local += __shfl_xor_sync(0xffffffffu, local, o);
    if (lane == 0) redsh[warp] = local;
    __syncthreads();
    if (tid == 0) {
        float ssq = 0.f;
#pragma unroll
        for (int i = 0; i < 16; i++) ssq += redsh[i];
        float inv = rsqrtf(fmaxf(ssq, 1e-12f));
        float n = sqrtf(fmaxf(ssq * inv * inv * (MAP_SCALE*MAP_SCALE), 1e-15f));
        float th = tanhf(n);
        float factor = (th > MAX_NORM) ? (MAX_NORM / th) : 1.0f;
        float nf = th * factor;
        x2sh = nf * nf;
        redsh[0] = inv * MAP_SCALE * (th / n) * factor;
    }
    __syncthreads();
    float coeffq = redsh[0];
    if (tid < 384) {
        float2 q = ((float2*)qsh4)[tid];
        ((float2*)qsh4)[tid] = make_float2(q.x * coeffq, q.y * coeffq);
    }
    __syncthreads();
    float x2 = x2sh;

    // ---- warp-per-key dot (pkey now L2-hot from the prologue) ----
    for (int p = warp; p < PP; p += 16) {
        const float4* kr = pkey + (size_t)p * D4;
        float dot = 0.f;
#pragma unroll
        for (int i = 0; i < 6; i++) {
            int j = lane + 32 * i;
            float4 kv = kr[j];
            float4 qv = qsh4[j];
            dot += kv.x*qv.x + kv.y*qv.y + kv.z*qv.z + kv.w*qv.w;
        }
#pragma unroll
        for (int o = 16; o > 0; o >>= 1) dot += __shfl_xor_sync(0xffffffffu, dot, o);
        if (lane == 0) {
            float ssq = kssq[p];
            float inv = rsqrtf(fmaxf(ssq, 1e-12f));
            float n = sqrtf(fmaxf(ssq * inv * inv * (MAP_SCALE*MAP_SCALE), 1e-15f));
            float th = tanhf(n);
            float factor = (th > MAX_NORM) ? (MAX_NORM / th) : 1.0f;
            float coeffk = inv * MAP_SCALE * (th / n) * factor;
            float nf = th * factor;
            float y2 = nf * nf;
            if (b == 0) g_kcoef[p] = coeffk;   // publish once for k3
            float xy = dot * coeffk;           // dot(q_ball, key_ball)
            float A   = 1.f - 2.f*xy + y2;
            float Bc  = 1.f - x2;
            float den = fmaxf(1.f - 2.f*xy + x2*y2, 1e-15f);
            float n2  = (A*A*x2 - 2.f*A*Bc*xy + Bc*Bc*y2) / (den*den);
            float nn  = sqrtf(fmaxf(n2, 1e-15f));
            nn = fminf(nn, 1.f - 1e-7f);
            float dist = 2.f * atanhf(nn);
            dsh[p] = dist;
            out[OFF_SIM + (long long)b * PP + p] = -dist;
        }
    }
    __syncthreads();

    // ---- top-K (smallest dist), sorted idx, per-batch selected sum ----
    if (tid == 0) {
        int sel[KK];
        bool used[PP];
        for (int p = 0; p < PP; p++) used[p] = false;
        float sum = 0.f;
        for (int k = 0; k < KK; k++) {
            float best = 1e30f; int bi = 0;
            for (int p = 0; p < PP; p++)
                if (!used[p] && dsh[p] < best) { best = dsh[p]; bi = p; }
            used[bi] = true; sel[k] = bi; sum += best;
        }
        for (int i = 0; i < KK; i++)
            for (int j = i + 1; j < KK; j++)
                if (sel[j] < sel[i]) { int t2 = sel[i]; sel[i] = sel[j]; sel[j] = t2; }
        for (int k = 0; k < KK; k++) {
            g_idx[b * KK + k] = sel[k];
            out[OFF_IDX + (long long)b * KK + k] = (float)sel[k];
        }
        g_persum[b] = sum;
    }
    __syncthreads();
#if __CUDA_ARCH__ >= 900
    cudaTriggerProgrammaticLaunchCompletion();
#endif
}

// ---------------------------------------------------------------------------
// Kernel 3: PDL secondary. gather prompt[idx] + selected_key + reduce_sim.
// grid (30, BB) = 3840 blocks x 192 threads (best-measured shape, R9/R11).
// ---------------------------------------------------------------------------
__global__ void k3_gather(const float4* __restrict__ prompt,
                          const float* __restrict__ pkey,
                          float* __restrict__ out) {
#if __CUDA_ARCH__ >= 900
    cudaGridDependencySynchronize();   // k2's g_idx/g_kcoef/g_persum visible
#endif
    int r = blockIdx.x, b = blockIdx.y, t = threadIdx.x;
    if (r < KK*LL) {
        int k = r / LL, l = r % LL;
        int j = g_idx[b * KK + k];
        float4 v = prompt[((size_t)j * LL + l) * D4 + t];
        ((float4*)out)[((size_t)b * SEQ_OUT + r) * D4 + t] = v;
    } else {
        int k = r - KK*LL;
        int j = g_idx[b * KK + k];
        float coeffk = g_kcoef[j];
        const float* kr = pkey + (size_t)j * DD;
        float* sk = out + OFF_SK + ((size_t)b * KK + k) * DD;
#pragma unroll
        for (int i = t; i < DD; i += 192) sk[i] = kr[i] * coeffk;
    }
    if (r == 0 && b == 0 && t == 0) {
        float s = 0.f;
#pragma unroll 8
        for (int i = 0; i < BB; i++) s += g_persum[i];
        out[OFF_RS] = s * (1.0f / (float)BB);
    }
}

extern "C" void kernel_launch(void* const* d_in, const int* in_sizes, int n_in,
                              void* d_out, int out_size) {
    const float* x_embed = nullptr;    // 128*512*768
    const float* prompt = nullptr;     // 60*5*768
    const float* prompt_key = nullptr; // 60*768
    for (int i = 0; i < n_in; i++) {
        if (in_sizes[i] == BB*SS*DD)        x_embed    = (const float*)d_in[i];
        else if (in_sizes[i] == PP*LL*DD)   prompt     = (const float*)d_in[i];
        else if (in_sizes[i] == PP*DD)      prompt_key = (const float*)d_in[i];
    }
    float* out = (float*)d_out;

    // k1: plain launch
    dim3 g1(NCHUNK, BB);
    k1_copy_partial<<<g1, D4>>>((const float4*)x_embed, (float4*)out);

    // k2: PDL secondary (may launch while k1 drains)
    {
        cudaLaunchConfig_t cfg = {};
        cfg.gridDim = dim3(BB, 1, 1);
        cfg.blockDim = dim3(512, 1, 1);
        cudaLaunchAttribute attr[1];
        attr[0].id = cudaLaunchAttributeProgrammaticStreamSerialization;
        attr[0].val.programmaticStreamSerializationAllowed = 1;
        cfg.attrs = attr;
        cfg.numAttrs = 1;
        cudaLaunchKernelEx(&cfg, k2_dist_topk, (const float4*)prompt_key, out);
    }

    // k3: PDL secondary (may launch while k2 drains)
    {
        cudaLaunchConfig_t cfg = {};
        cfg.gridDim = dim3(KK*LL + KK, BB, 1);
        cfg.blockDim = dim3(D4, 1, 1);
        cudaLaunchAttribute attr[1];
        attr[0].id = cudaLaunchAttributeProgrammaticStreamSerialization;
        attr[0].val.programmaticStreamSerializationAllowed = 1;
        cfg.attrs = attr;
        cfg.numAttrs = 1;
        cudaLaunchKernelEx(&cfg, k3_gather, (const float4*)prompt,
                           (const float*)prompt_key, out);
    }
}

// round 17
// speedup vs baseline: 1.0454x; 1.0283x over previous
#include <cuda_runtime.h>
#include <math.h>

#define BB 128
#define SS 512
#define DD 768
#define PP 60
#define LL 5
#define KK 5
#define D4 (DD/4)            // 192
#define SEQ_OUT (KK*LL + SS) // 537
#define NCHUNK 16
#define CHUNK_S (SS/NCHUNK)  // 32

#define MAP_SCALE 0.1f
#define MAX_NORM (1.0f - 4e-3f)

// Output layout (float32, concatenated in reference return order)
#define N_PE    ((long long)BB*SEQ_OUT*DD)           // 52,801,536
#define OFF_RS  (N_PE)
#define OFF_IDX (OFF_RS + 1)
#define OFF_SIM (OFF_IDX + (long long)BB*KK)
#define OFF_SK  (OFF_SIM + (long long)BB*PP)

// Scratch (device globals -> no allocation). Flags zero-init; each is reset by
// its single consumer every iteration -> deterministic across graph replays.
__device__ float g_xpart[BB*NCHUNK*DD];
__device__ float g_selcoef[BB*KK];
__device__ float g_persum[BB];
__device__ int   g_idx[BB*KK];
__device__ int   g_cnt[BB];     // k1 -> k2 per-batch chunk counter
__device__ int   g_ready[BB];   // k2 -> k3 per-batch flag
__device__ int   g_done;        // k2 -> reduce_sim counter

// ---------------------------------------------------------------------------
// Kernel 1: copy + partials. Trigger at block START so k2's grid launches as
// soon as all k1 blocks have started (≈ half-way), not when k1 finishes.
// Hot loop untouched (32 regs, 76% DRAM). Release: fence -> sync -> atomic.
// ---------------------------------------------------------------------------
__global__ void k1_copy_partial(const float4* __restrict__ xe, float4* __restrict__ out) {
#if __CUDA_ARCH__ >= 900
    cudaTriggerProgrammaticLaunchCompletion();
#endif
    int chunk = blockIdx.x, b = blockIdx.y, t = threadIdx.x;
    const float4* src = xe + ((size_t)b * SS + (size_t)chunk * CHUNK_S) * D4 + t;
    float4* dst = out + ((size_t)b * SEQ_OUT + KK*LL + (size_t)chunk * CHUNK_S) * D4 + t;
    float4 acc = make_float4(0.f, 0.f, 0.f, 0.f);
#pragma unroll 8
    for (int s = 0; s < CHUNK_S; s++) {
        float4 v = src[(size_t)s * D4];
        acc.x += v.x; acc.y += v.y; acc.z += v.z; acc.w += v.w;
        dst[(size_t)s * D4] = v;
    }
    ((float4*)g_xpart)[(b * NCHUNK + chunk) * D4 + t] = acc;
    __threadfence();
    __syncthreads();
    if (t == 0) atomicAdd(&g_cnt[b], 1);
}

// ---------------------------------------------------------------------------
// Kernel 2: PDL secondary, one block per batch (512 thr). Prologue (key ssq)
// is k1-independent; then spin until this batch's 16 chunks are published.
// Publishes g_idx / g_selcoef / g_persum, sets g_ready[b]. Triggers at start
// so k3 can launch and spin.
// ---------------------------------------------------------------------------
__global__ void k2_dist_topk(const float4* __restrict__ pkey, float* __restrict__ out) {
#if __CUDA_ARCH__ >= 900
    cudaTriggerProgrammaticLaunchCompletion();
#endif
    int b = blockIdx.x;
    int tid = threadIdx.x, lane = tid & 31, warp = tid >> 5;
    __shared__ float4 qsh4[D4];
    __shared__ float dsh[PP];
    __shared__ float csh[PP];
    __shared__ float kssq[PP];
    __shared__ float redsh[16];
    __shared__ float x2sh;

    // ---- independent prologue: per-key ssq (warms L2 with pkey) ----
    for (int p = warp; p < PP; p += 16) {
        const float4* kr = pkey + (size_t)p * D4;
        float ssq = 0.f;
#pragma unroll
        for (int i = 0; i < 6; i++) {
            float4 kv = kr[lane + 32 * i];
            ssq += kv.x*kv.x + kv.y*kv.y + kv.z*kv.z + kv.w*kv.w;
        }
#pragma unroll
        for (int o = 16; o > 0; o >>= 1) ssq += __shfl_xor_sync(0xffffffffu, ssq, o);
        if (lane == 0) kssq[p] = ssq;
    }

    // ---- acquire this batch's partials (spin on per-batch counter) ----
    if (tid == 0) {
        while (atomicAdd(&g_cnt[b], 0) < NCHUNK) __nanosleep(64);
        g_cnt[b] = 0;                 // single consumer -> safe reset
    }
    __syncthreads();
    __threadfence();

    // ---- mean from partials (threads 0..383, 2 dims each) ----
    float local = 0.f;
    if (tid < 384) {
        float sx = 0.f, sy = 0.f;
        const float2* pp = (const float2*)g_xpart;
#pragma unroll
        for (int c = 0; c < NCHUNK; c++) {
            float2 a = pp[(size_t)(b * NCHUNK + c) * (DD/2) + tid];
            sx += a.x; sy += a.y;
        }
        sx *= (1.0f / (float)SS);
        sy *= (1.0f / (float)SS);
        ((float2*)qsh4)[tid] = make_float2(sx, sy);
        local = sx*sx + sy*sy;
    }
#pragma unroll
    for (int o = 16; o > 0; o >>= 1) local += __shfl_xor_sync(0xffffffffu, local, o);
    if (lane == 0) redsh[warp] = local;
    __syncthreads();
    if (tid == 0) {
        float ssq = 0.f;
#pragma unroll
        for (int i = 0; i < 16; i++) ssq += redsh[i];
        float inv = rsqrtf(fmaxf(ssq, 1e-12f));
        float n = sqrtf(fmaxf(ssq * inv * inv * (MAP_SCALE*MAP_SCALE), 1e-15f));
        float th = tanhf(n);
        float factor = (th > MAX_NORM) ? (MAX_NORM / th) : 1.0f;
        float nf = th * factor;
        x2sh = nf * nf;
        redsh[0] = inv * MAP_SCALE * (th / n) * factor;
    }
    __syncthreads();
    float coeffq = redsh[0];
    if (tid < 384) {
        float2 q = ((float2*)qsh4)[tid];
        ((float2*)qsh4)[tid] = make_float2(q.x * coeffq, q.y * coeffq);
    }
    __syncthreads();
    float x2 = x2sh;

    // ---- warp-per-key dot (pkey L2-hot) ----
    for (int p = warp; p < PP; p += 16) {
        const float4* kr = pkey + (size_t)p * D4;
        float dot = 0.f;
#pragma unroll
        for (int i = 0; i < 6; i++) {
            int j = lane + 32 * i;
            float4 kv = kr[j];
            float4 qv = qsh4[j];
            dot += kv.x*qv.x + kv.y*qv.y + kv.z*qv.z + kv.w*qv.w;
        }
#pragma unroll
        for (int o = 16; o > 0; o >>= 1) dot += __shfl_xor_sync(0xffffffffu, dot, o);
        if (lane == 0) {
            float ssq = kssq[p];
            float inv = rsqrtf(fmaxf(ssq, 1e-12f));
            float n = sqrtf(fmaxf(ssq * inv * inv * (MAP_SCALE*MAP_SCALE), 1e-15f));
            float th = tanhf(n);
            float factor = (th > MAX_NORM) ? (MAX_NORM / th) : 1.0f;
            float coeffk = inv * MAP_SCALE * (th / n) * factor;
            float nf = th * factor;
            float y2 = nf * nf;
            float xy = dot * coeffk;           // dot(q_ball, key_ball)
            float A   = 1.f - 2.f*xy + y2;
            float Bc  = 1.f - x2;
            float den = fmaxf(1.f - 2.f*xy + x2*y2, 1e-15f);
            float n2  = (A*A*x2 - 2.f*A*Bc*xy + Bc*Bc*y2) / (den*den);
            float nn  = sqrtf(fmaxf(n2, 1e-15f));
            nn = fminf(nn, 1.f - 1e-7f);
            float dist = 2.f * atanhf(nn);
            dsh[p] = dist;
            csh[p] = coeffk;
            out[OFF_SIM + (long long)b * PP + p] = -dist;
        }
    }
    __syncthreads();

    // ---- top-K, sorted idx, publish per-batch results + ready flag ----
    if (tid == 0) {
        int sel[KK];
        bool used[PP];
        for (int p = 0; p < PP; p++) used[p] = false;
        float sum = 0.f;
        for (int k = 0; k < KK; k++) {
            float best = 1e30f; int bi = 0;
            for (int p = 0; p < PP; p++)
                if (!used[p] && dsh[p] < best) { best = dsh[p]; bi = p; }
            used[bi] = true; sel[k] = bi; sum += best;
        }
        for (int i = 0; i < KK; i++)
            for (int j = i + 1; j < KK; j++)
                if (sel[j] < sel[i]) { int t2 = sel[i]; sel[i] = sel[j]; sel[j] = t2; }
        for (int k = 0; k < KK; k++) {
            g_idx[b * KK + k] = sel[k];
            g_selcoef[b * KK + k] = csh[sel[k]];
            out[OFF_IDX + (long long)b * KK + k] = (float)sel[k];
        }
        g_persum[b] = sum;
        __threadfence();                    // publish tid0's writes
        atomicExch(&g_ready[b], 1);
        atomicAdd(&g_done, 1);
    }
}

// ---------------------------------------------------------------------------
// Kernel 3: PDL secondary, one block per batch (512 thr). Spins on its batch's
// ready flag, gathers prompt rows + selected_key. Block 0 additionally waits
// for all batches and computes reduce_sim. Each block resets its own flag.
// ---------------------------------------------------------------------------
__global__ void k3_gather(const float4* __restrict__ prompt,
                          const float* __restrict__ pkey,
                          float* __restrict__ out) {
    int b = blockIdx.x, tid = threadIdx.x;
    __shared__ int   ish[KK];
    __shared__ float csh[KK];
    if (tid == 0) {
        while (atomicAdd(&g_ready[b], 0) == 0) __nanosleep(64);
        g_ready[b] = 0;                 // single consumer -> safe reset
    }
    __syncthreads();
    __threadfence();
    if (tid < KK) {
        ish[tid] = g_idx[b * KK + tid];
        csh[tid] = g_selcoef[b * KK + tid];
    }
    __syncthreads();

    // prompt rows: 25 rows x 192 float4
#pragma unroll
    for (int i = tid; i < KK*LL*D4; i += 512) {
        int r = i / D4, c = i % D4;
        int j = ish[r / LL];
        float4 v = prompt[((size_t)j * LL + (r % LL)) * D4 + c];
        ((float4*)out)[((size_t)b * SEQ_OUT + r) * D4 + c] = v;
    }
    // selected_key: 5 x 768 scalars (odd base offset)
#pragma unroll
    for (int i = tid; i < KK*DD; i += 512) {
        int k = i / DD, c = i % DD;
        out[OFF_SK + (size_t)b * KK * DD + i] =
            pkey[(size_t)ish[k] * DD + c] * csh[k];
    }

    if (b == 0 && tid == 0) {
        while (atomicAdd(&g_done, 0) < BB) __nanosleep(64);
        g_done = 0;                     // single consumer -> safe reset
        __threadfence();
        float s = 0.f;
#pragma unroll 8
        for (int i = 0; i < BB; i++) s += g_persum[i];
        out[OFF_RS] = s * (1.0f / (float)BB);
    }
}

extern "C" void kernel_launch(void* const* d_in, const int* in_sizes, int n_in,
                              void* d_out, int out_size) {
    const float* x_embed = nullptr;    // 128*512*768
    const float* prompt = nullptr;     // 60*5*768
    const float* prompt_key = nullptr; // 60*768
    for (int i = 0; i < n_in; i++) {
        if (in_sizes[i] == BB*SS*DD)        x_embed    = (const float*)d_in[i];
        else if (in_sizes[i] == PP*LL*DD)   prompt     = (const float*)d_in[i];
        else if (in_sizes[i] == PP*DD)      prompt_key = (const float*)d_in[i];
    }
    float* out = (float*)d_out;

    // k1: plain launch
    dim3 g1(NCHUNK, BB);
    k1_copy_partial<<<g1, D4>>>((const float4*)x_embed, (float4*)out);

    // k2: PDL secondary — launches once all k1 blocks have STARTED
    {
        cudaLaunchConfig_t cfg = {};
        cfg.gridDim = dim3(BB, 1, 1);
        cfg.blockDim = dim3(512, 1, 1);
        cudaLaunchAttribute attr[1];
        attr[0].id = cudaLaunchAttributeProgrammaticStreamSerialization;
        attr[0].val.programmaticStreamSerializationAllowed = 1;
        cfg.attrs = attr;
        cfg.numAttrs = 1;
        cudaLaunchKernelEx(&cfg, k2_dist_topk, (const float4*)prompt_key, out);
    }

    // k3: PDL secondary — launches once all k2 blocks have STARTED
    {
        cudaLaunchConfig_t cfg = {};
        cfg.gridDim = dim3(BB, 1, 1);
        cfg.blockDim = dim3(512, 1, 1);
        cudaLaunchAttribute attr[1];
        attr[0].id = cudaLaunchAttributeProgrammaticStreamSerialization;
        attr[0].val.programmaticStreamSerializationAllowed = 1;
        cfg.attrs = attr;
        cfg.numAttrs = 1;
        cudaLaunchKernelEx(&cfg, k3_gather, (const float4*)prompt,
                           (const float*)prompt_key, out);
    }
}